// round 8
// baseline (speedup 1.0000x reference)
#include <cuda_runtime.h>
#include <math.h>

// Problem constants (fixed by the reference)
#define N_BAGS   64
#define GRID_W   96
#define NQ       512
#define NMEM     131072
#define DIM      256

#define NBLK     128
#define NTHR     512
#define NTHREADS (NBLK * NTHR)                 // 65536
#define NTASK    (NQ * 8)                      // 4096 (query, neighbor) inserts

#define HBITS    14
#define HSIZE    (1 << HBITS)                  // 16384 slots (load factor 0.25)
#define HMASK    (HSIZE - 1)
#define MAXM     8                             // max matches recorded per row

// Scratch: device globals (no runtime allocation allowed).
__device__ unsigned long long g_hash[HSIZE];   // (cell+1)<<32 | qi ; 0 = empty
__device__ float              g_inv[NQ];       // 5 / ||q_i||

// ---- software grid barrier (128 CTAs co-resident by construction) ----
__device__ unsigned          g_bar_cnt[4];
__device__ volatile unsigned g_bar_gen[4];

__device__ __forceinline__ void grid_sync(int id) {
    __syncthreads();
    if (threadIdx.x == 0) {
        __threadfence();
        unsigned gen = g_bar_gen[id];
        if (atomicAdd(&g_bar_cnt[id], 1u) == (unsigned)(gridDim.x - 1)) {
            g_bar_cnt[id] = 0;
            __threadfence();
            g_bar_gen[id] = gen + 1;           // release
        } else {
            while (g_bar_gen[id] == gen) { __nanosleep(32); }
        }
        __threadfence();
    }
    __syncthreads();
}

__device__ __forceinline__ unsigned cell_hash(int cell) {
    return ((unsigned)cell * 2654435761u) >> (32 - HBITS);
}

__device__ __forceinline__ int neighbor_cell(int bag, int x0, int y0, int nb,
                                             bool& valid) {
    int idx = nb + (nb >= 4 ? 1 : 0);          // 0..8 skipping center (4)
    int dx = idx % 3 - 1;
    int dy = idx / 3 - 1;
    int x = x0 + dx, y = y0 + dy;
    valid = (x >= 0) & (x < GRID_W) & (y >= 0) & (y < GRID_W);
    return (bag * GRID_W + y) * GRID_W + x;
}

// ---------------------------------------------------------------------------
// Single fused kernel, query-side hashing:
//   P0a: zero hash + out, compute g_inv (warp per query; warms q into L2)
//   P0b: insert 4096 (neighbor-cell -> qi) entries (atomicCAS linear probe)
//   P1 : stream all memory rows; probe hash; warp-cooperative dot+exp on hits
// ---------------------------------------------------------------------------
__global__ void __launch_bounds__(NTHR, 1)
fused_kernel(const float* __restrict__ q,
             const float* __restrict__ memory,
             const int*   __restrict__ bag_idx,
             const int*   __restrict__ xc,
             const int*   __restrict__ yc,
             const int*   __restrict__ bag_idxs,
             const int*   __restrict__ xs,
             const int*   __restrict__ ys,
             float*       __restrict__ out) {
    const unsigned FULL = 0xFFFFFFFFu;
    int tid  = blockIdx.x * NTHR + threadIdx.x;          // 0 .. 65535
    int lane = threadIdx.x & 31;
    int warp = tid >> 5;                                  // 0 .. 2047

    // ---- Phase 0a: zero hash + out; per-query inverse norms ----
    if (tid < HSIZE) g_hash[tid] = 0ULL;
    if (tid < NQ)    out[tid] = 0.0f;
    if (warp < NQ) {
        const float* qr = q + warp * DIM + lane * 8;
        float4 a = *(const float4*)(qr);
        float4 b = *(const float4*)(qr + 4);
        float ss = a.x * a.x + a.y * a.y + a.z * a.z + a.w * a.w
                 + b.x * b.x + b.y * b.y + b.z * b.z + b.w * b.w;
        #pragma unroll
        for (int o = 16; o; o >>= 1) ss += __shfl_xor_sync(FULL, ss, o);
        if (lane == 0) g_inv[warp] = rsqrtf(ss) * 5.0f;   // 1/(||q||*0.2)
    }
    grid_sync(0);

    // ---- Phase 0b: insert the 4096 (cell -> qi) entries ----
    if (tid < NTASK) {
        int qi = tid >> 3, nb = tid & 7;
        bool valid;
        int cell = neighbor_cell(bag_idx[qi], xc[qi], yc[qi], nb, valid);
        if (valid) {
            unsigned long long packed =
                ((unsigned long long)(unsigned)(cell + 1) << 32) | (unsigned)qi;
            unsigned h = cell_hash(cell);
            #pragma unroll 1
            for (int it = 0; it < HSIZE; it++) {
                if (atomicCAS(&g_hash[h], 0ULL, packed) == 0ULL) break;
                h = (h + 1) & HMASK;
            }
        }
    }
    grid_sync(1);

    // ---- Phase 1: stream memory rows, probe, warp-cooperative hits ----
    #pragma unroll
    for (int r = 0; r < NMEM / NTHREADS; r++) {           // 2 rows / thread
        int nrow = tid + r * NTHREADS;

        int cell = (bag_idxs[nrow] * GRID_W + ys[nrow]) * GRID_W + xs[nrow];
        unsigned keyhi = (unsigned)(cell + 1);

        // walk the chain, record matching queries
        int m = 0;
        int qmatch[MAXM];
        unsigned h = cell_hash(cell);
        #pragma unroll 1
        for (int it = 0; it < HSIZE; it++) {
            unsigned long long e = g_hash[h];
            if (e == 0ULL) break;
            if ((unsigned)(e >> 32) == keyhi && m < MAXM)
                qmatch[m++] = (int)(unsigned)e;
            h = (h + 1) & HMASK;
        }

        // warp-cooperative processing of all matches in this warp
        while (true) {
            unsigned ball = __ballot_sync(FULL, m > 0);
            if (!ball) break;
            int src  = __ffs(ball) - 1;
            int top  = (m > 0) ? qmatch[m - 1] : 0;
            int qi_b = __shfl_sync(FULL, top, src);
            int n_b  = __shfl_sync(FULL, nrow, src);

            const float* mr = memory + (size_t)n_b * DIM + lane * 8;
            float4 m0 = *(const float4*)(mr);
            float4 m1 = *(const float4*)(mr + 4);
            const float* qr = q + qi_b * DIM + lane * 8;
            float4 a = *(const float4*)(qr);
            float4 b = *(const float4*)(qr + 4);

            float d = a.x * m0.x + a.y * m0.y + a.z * m0.z + a.w * m0.w
                    + b.x * m1.x + b.y * m1.y + b.z * m1.z + b.w * m1.w;
            #pragma unroll
            for (int o = 16; o; o >>= 1) d += __shfl_xor_sync(FULL, d, o);

            if (lane == src) {
                m--;
                atomicAdd(&out[qi_b], expf(d * g_inv[qi_b]));
            }
        }
    }
}

extern "C" void kernel_launch(void* const* d_in, const int* in_sizes, int n_in,
                              void* d_out, int out_size) {
    const float* q        = (const float*)d_in[0];   // [512, 256]
    const float* memory   = (const float*)d_in[1];   // [131072, 256]
    const int*   bag_idx  = (const int*)d_in[2];     // [512]
    const int*   x_coord  = (const int*)d_in[3];     // [512]
    const int*   y_coord  = (const int*)d_in[4];     // [512]
    const int*   bag_idxs = (const int*)d_in[5];     // [131072]
    const int*   x_coords = (const int*)d_in[6];     // [131072]
    const int*   y_coords = (const int*)d_in[7];     // [131072]
    float* out = (float*)d_out;                      // [512]

    fused_kernel<<<NBLK, NTHR>>>(q, memory, bag_idx, x_coord, y_coord,
                                 bag_idxs, x_coords, y_coords, out);
}

// round 9
// speedup vs baseline: 1.6354x; 1.6354x over previous
#include <cuda_runtime.h>
#include <math.h>

// Problem constants (fixed by the reference)
#define N_BAGS   64
#define GRID_W   96
#define NCELLS   (N_BAGS * GRID_W * GRID_W)   // 589824
#define CAP      16        // bucket capacity; Poisson(0.222) => overflow ~impossible
#define NQ       512
#define NMEM     131072
#define DIM      256

#define NBLK     128
#define NTHR     1024
#define NTASK    (NQ * 8)                      // 4096 tasks == 4096 warps

// Scratch: device globals (no runtime allocation allowed).
// Counter word = (epoch << 8) | cnt. Zero-init == epoch 0, cnt 0 -> launch 0
// sees every cell as valid-empty. g_epoch bumps once per launch, so stale
// cells (old epoch tag) read as empty without any zeroing pass.
__device__ unsigned g_cnt[NCELLS];
__device__ int      g_cell_items[NCELLS * CAP];
__device__ unsigned g_epoch;

// ---- software grid barrier (128 CTAs, all co-resident by construction) ----
__device__ unsigned          g_bar_cnt;
__device__ volatile unsigned g_bar_gen;

__device__ __forceinline__ void grid_sync() {
    __syncthreads();
    if (threadIdx.x == 0) {
        __threadfence();
        unsigned gen = g_bar_gen;
        if (atomicAdd(&g_bar_cnt, 1u) == (unsigned)(gridDim.x - 1)) {
            g_bar_cnt = 0;
            __threadfence();
            g_bar_gen = gen + 1;               // release
        } else {
            while (g_bar_gen == gen) { }       // spin (volatile load)
        }
        __threadfence();
    }
    __syncthreads();
}

__device__ __forceinline__ int neighbor_cell(int bag, int x0, int y0, int nb,
                                             bool& valid) {
    int idx = nb + (nb >= 4 ? 1 : 0);          // 0..8 skipping center (4)
    int dx = idx % 3 - 1;
    int dy = idx / 3 - 1;
    int x = x0 + dx, y = y0 + dy;
    valid = (x >= 0) & (x < GRID_W) & (y >= 0) & (y < GRID_W);
    return (bag * GRID_W + y) * GRID_W + x;
}

// ---------------------------------------------------------------------------
// Single fused kernel, ONE grid barrier:
//   P1: each thread scatters exactly one memory row (epoch-tagged slot claim);
//       threads < NQ also zero out[]. -> barrier ->
//   P2: one warp per (query, neighbor-cell) task; pipelined row fetches.
// ---------------------------------------------------------------------------
__global__ void __launch_bounds__(NTHR, 1)
fused_kernel(const float* __restrict__ q,
             const float* __restrict__ memory,
             const int*   __restrict__ bag_idx,
             const int*   __restrict__ xc,
             const int*   __restrict__ yc,
             const int*   __restrict__ bag_idxs,
             const int*   __restrict__ xs,
             const int*   __restrict__ ys,
             float*       __restrict__ out) {
    const unsigned FULL = 0xFFFFFFFFu;
    int tid  = blockIdx.x * NTHR + threadIdx.x;          // 0 .. 131071
    int lane = threadIdx.x & 31;

    unsigned epoch = g_epoch;                            // uniform
    unsigned tag   = epoch << 8;

    // ---- Phase 1: scatter my one memory row; zero out[] ----
    if (tid < NQ) out[tid] = 0.0f;
    {
        int n = tid;                                     // exactly NMEM threads
        int cell = (bag_idxs[n] * GRID_W + ys[n]) * GRID_W + xs[n];
        unsigned cur = g_cnt[cell];
        int slot;
        for (;;) {
            if ((cur & 0xFFFFFF00u) == tag) {            // current epoch: plain add
                unsigned old = atomicAdd(&g_cnt[cell], 1u);
                // once current-epoch, a cell stays current within this launch
                slot = (int)(old & 0xFFu);
                break;
            }
            // stale: try to claim the reset (first writer wins, slot 0)
            unsigned prev = atomicCAS(&g_cnt[cell], cur, tag | 1u);
            if (prev == cur) { slot = 0; break; }
            cur = prev;                                  // retry with fresh value
        }
        if (slot < CAP) g_cell_items[cell * CAP + slot] = n;
    }
    grid_sync();

    // bump epoch for the next launch (all reads of g_epoch happened pre-barrier)
    if (tid == 0) { g_epoch = epoch + 1; __threadfence(); }

    // ---- Phase 2: one warp per (query, neighbor-cell) task ----
    int task = tid >> 5;                                 // 0 .. 4095 == NTASK
    int qi   = task >> 3;
    int nb   = task & 7;

    // Issue the query-row load early so it overlaps the probe chain.
    const float* qrow = q + qi * DIM + lane * 8;
    float4 a = *(const float4*)(qrow);
    float4 b = *(const float4*)(qrow + 4);

    bool valid;
    int cell = neighbor_cell(bag_idx[qi], xc[qi], yc[qi], nb, valid);
    if (!valid) return;

    unsigned word = g_cnt[cell];
    int cnt = ((word & 0xFFFFFF00u) == tag) ? (int)(word & 0xFFu) : 0;
    if (cnt > CAP) cnt = CAP;
    if (cnt == 0) return;

    // All item loads in parallel: lane i holds item i.
    int item = (lane < cnt) ? g_cell_items[cell * CAP + lane] : 0;

    // ||q||^2 warp reduce (overlaps the loads above).
    float ss = a.x * a.x + a.y * a.y + a.z * a.z + a.w * a.w
             + b.x * b.x + b.y * b.y + b.z * b.z + b.w * b.w;
    #pragma unroll
    for (int o = 16; o; o >>= 1) ss += __shfl_xor_sync(FULL, ss, o);
    float inv = rsqrtf(ss) * 5.0f;                       // 1 / (||q|| * 0.2)

    float s = 0.0f;
    for (int c0 = 0; c0 < cnt; c0 += 4) {
        int k = cnt - c0; if (k > 4) k = 4;
        float d[4];
        #pragma unroll
        for (int j = 0; j < 4; j++) {
            int ci = c0 + j; if (ci >= cnt) ci = cnt - 1;   // dup last (cached)
            int n = __shfl_sync(FULL, item, ci);
            const float* mr = memory + (size_t)n * DIM + lane * 8;
            float4 m0 = *(const float4*)(mr);
            float4 m1 = *(const float4*)(mr + 4);
            d[j] = a.x * m0.x + a.y * m0.y + a.z * m0.z + a.w * m0.w
                 + b.x * m1.x + b.y * m1.y + b.z * m1.z + b.w * m1.w;
        }
        #pragma unroll
        for (int o = 16; o; o >>= 1) {                   // 4 interleaved reductions
            d[0] += __shfl_xor_sync(FULL, d[0], o);
            d[1] += __shfl_xor_sync(FULL, d[1], o);
            d[2] += __shfl_xor_sync(FULL, d[2], o);
            d[3] += __shfl_xor_sync(FULL, d[3], o);
        }
        #pragma unroll
        for (int j = 0; j < 4; j++)
            if (j < k) s += expf(d[j] * inv);
    }
    if (lane == 0) atomicAdd(&out[qi], s);
}

extern "C" void kernel_launch(void* const* d_in, const int* in_sizes, int n_in,
                              void* d_out, int out_size) {
    const float* q        = (const float*)d_in[0];   // [512, 256]
    const float* memory   = (const float*)d_in[1];   // [131072, 256]
    const int*   bag_idx  = (const int*)d_in[2];     // [512]
    const int*   x_coord  = (const int*)d_in[3];     // [512]
    const int*   y_coord  = (const int*)d_in[4];     // [512]
    const int*   bag_idxs = (const int*)d_in[5];     // [131072]
    const int*   x_coords = (const int*)d_in[6];     // [131072]
    const int*   y_coords = (const int*)d_in[7];     // [131072]
    float* out = (float*)d_out;                      // [512]

    fused_kernel<<<NBLK, NTHR>>>(q, memory, bag_idx, x_coord, y_coord,
                                 bag_idxs, x_coords, y_coords, out);
}